// round 5
// baseline (speedup 1.0000x reference)
#include <cuda_runtime.h>
#include <cstdint>
#include <math.h>

#define NN 50000
#define EE 600000
#define DD 128
#define GG 128

// ---------------- device scratch ----------------
__device__ float g_y0[NN * DD];
__device__ float g_y1[NN * DD];
__device__ int   g_deg[NN];
__device__ int   g_fill[NN];
__device__ float g_dinv[NN];
__device__ int   g_rowptr[NN + 1];
__device__ int   g_csrc[EE];
__device__ float g_cw[EE];
__device__ uint32_t g_wt[3][DD * DD];   // W^T, tf32 bits, permuted k-layout

__device__ __forceinline__ uint32_t f2tf32(float f) {
    uint32_t r;
    asm("cvt.rna.tf32.f32 %0, %1;" : "=r"(r) : "f"(f));
    return r;
}

__device__ __forceinline__ void mma_tf32(float c[4], const uint32_t a[4], const uint32_t b[2]) {
    asm volatile(
        "mma.sync.aligned.m16n8k8.row.col.f32.tf32.tf32.f32 "
        "{%0,%1,%2,%3}, {%4,%5,%6,%7}, {%8,%9}, {%0,%1,%2,%3};"
        : "+f"(c[0]), "+f"(c[1]), "+f"(c[2]), "+f"(c[3])
        : "r"(a[0]), "r"(a[1]), "r"(a[2]), "r"(a[3]), "r"(b[0]), "r"(b[1]));
}

// permute within 8-col group so (k, k+4) are adjacent: c -> (c&3)*2 + (c>>2)
__device__ __forceinline__ int kperm(int c) { return ((c & 3) << 1) | ((c >> 2) & 1); }

// ======================= CSR build =======================
__global__ void k_init() {
    int i = blockIdx.x * blockDim.x + threadIdx.x;
    if (i < NN) { g_deg[i] = 0; g_fill[i] = 0; }
}
__global__ void k_deg(const int* __restrict__ ei) {
    int e4 = (blockIdx.x * blockDim.x + threadIdx.x) << 2;
    if (e4 < EE) {
        int4 d = *(const int4*)(ei + EE + e4);
        atomicAdd(&g_deg[d.x], 1);
        atomicAdd(&g_deg[d.y], 1);
        atomicAdd(&g_deg[d.z], 1);
        atomicAdd(&g_deg[d.w], 1);
    }
}
__global__ void k_scan() {
    const int CH = (NN + 1023) / 1024;
    __shared__ int ss[1024];
    int t = threadIdx.x;
    int vals[CH];
    int base = t * CH;
    int loc = 0;
#pragma unroll
    for (int i = 0; i < CH; ++i) {
        int idx = base + i;
        int v = (idx < NN) ? g_deg[idx] : 0;
        if (idx < NN) g_dinv[idx] = rsqrtf((float)(v + 1));
        vals[i] = loc;
        loc += v;
    }
    ss[t] = loc;
    __syncthreads();
    for (int off = 1; off < 1024; off <<= 1) {
        int v = (t >= off) ? ss[t - off] : 0;
        __syncthreads();
        ss[t] += v;
        __syncthreads();
    }
    int pre = (t > 0) ? ss[t - 1] : 0;
#pragma unroll
    for (int i = 0; i < CH; ++i) {
        int idx = base + i;
        if (idx < NN) g_rowptr[idx] = pre + vals[i];
    }
    if (t == 1023) g_rowptr[NN] = ss[1023];
}
__global__ void k_fill(const int* __restrict__ ei) {
    int e = blockIdx.x * blockDim.x + threadIdx.x;
    if (e < EE) {
        int s = ei[e];
        int d = ei[EE + e];
        int pos = g_rowptr[d] + atomicAdd(&g_fill[d], 1);
        g_csrc[pos] = s;
        g_cw[pos] = g_dinv[s] * g_dinv[d];
    }
}

// ======================= W^T precompute =======================
__global__ void k_wt(const float* __restrict__ W0, const float* __restrict__ W1,
                     const float* __restrict__ W2) {
    const float* Ws[3] = {W0, W1, W2};
    int l = blockIdx.y;
    int i = blockIdx.x * blockDim.x + threadIdx.x;
    if (i < DD * DD) {
        int n = i >> 7;
        int kp = i & 127;
        int k = (kp & ~7) + ((kp & 7) >> 1) + ((kp & 1) << 2);  // inverse perm
        g_wt[l][i] = f2tf32(Ws[l][(size_t)k * DD + n]);
    }
}

// ======================= fused layer: gather-agg + tf32 GEMM + LN + SiLU ===========
// y = SiLU( LN( (A_norm @ xin) @ W + b )*g + be + xin )
// TILE_M=64; 8 warps 2(m)x4(n) for MMA; gather: warp w owns rows w*8..w*8+7.
#define TILE_M 64
#define SST 132
#define DYN_SMEM ((TILE_M + 128) * SST * 4)

__global__ void __launch_bounds__(256) k_layer(
    const float* __restrict__ xin, const uint32_t* __restrict__ Wt,
    const float* __restrict__ bias, const float* __restrict__ gamma,
    const float* __restrict__ beta, float* __restrict__ y) {
    extern __shared__ float smem[];
    float* As = smem;                     // [64][SST] permuted-k tf32; reused for C
    float* Bs = smem + TILE_M * SST;      // [128][SST]
    uint32_t* Asu = (uint32_t*)As;
    uint32_t* Bsu = (uint32_t*)Bs;
    __shared__ float s_b[128], s_g[128], s_be[128];

    int tid = threadIdx.x;
    int wid = tid >> 5;
    int lane = tid & 31;
    int m0 = blockIdx.x * TILE_M;

    if (tid < 128) { s_b[tid] = bias[tid]; s_g[tid] = gamma[tid]; s_be[tid] = beta[tid]; }

    // B tile: coalesced uint4 copy from pre-permuted Wt
    for (int i = tid; i < 128 * 32; i += 256) {
        int n = i >> 5;
        int c4 = (i & 31) << 2;
        *(uint4*)&Bsu[n * SST + c4] = *(const uint4*)&Wt[n * DD + c4];
    }

    // gather-aggregate A tile: warp handles 8 rows; lane holds cols 4*lane..+3
    int colb = lane * 4;
    int sbase = (colb & ~7);
    int g0 = colb & 7;                    // 0 or 4
    int p0 = sbase + kperm(g0 + 0);
    int p1 = sbase + kperm(g0 + 1);
    int p2 = sbase + kperm(g0 + 2);
    int p3 = sbase + kperm(g0 + 3);
#pragma unroll
    for (int rr = 0; rr < 8; ++rr) {
        int m = wid * 8 + rr;
        int row = m0 + m;
        float4 acc = make_float4(0.f, 0.f, 0.f, 0.f);
        if (row < NN) {
            float di = g_dinv[row];
            float sw = di * di;
            acc = *(const float4*)(xin + (size_t)row * DD + colb);
            acc.x *= sw; acc.y *= sw; acc.z *= sw; acc.w *= sw;
            int e0 = g_rowptr[row], e1 = g_rowptr[row + 1];
#pragma unroll 2
            for (int e = e0; e < e1; ++e) {
                int s = __ldg(&g_csrc[e]);
                float wt = __ldg(&g_cw[e]);
                float4 hs = *(const float4*)(xin + (size_t)s * DD + colb);
                acc.x += wt * hs.x; acc.y += wt * hs.y;
                acc.z += wt * hs.z; acc.w += wt * hs.w;
            }
        }
        uint32_t* arow = Asu + m * SST;
        arow[p0] = f2tf32(acc.x);
        arow[p1] = f2tf32(acc.y);
        arow[p2] = f2tf32(acc.z);
        arow[p3] = f2tf32(acc.w);
    }
    __syncthreads();

    const int wm = (wid >> 2) * 32;
    const int wn = (wid & 3) * 32;
    const int qrow = lane >> 2;
    const int qcol = lane & 3;

    float c[2][4][4];
#pragma unroll
    for (int mt = 0; mt < 2; ++mt)
#pragma unroll
        for (int nt = 0; nt < 4; ++nt)
#pragma unroll
            for (int j = 0; j < 4; ++j) c[mt][nt][j] = 0.f;

#pragma unroll
    for (int ks = 0; ks < 16; ++ks) {
        int k0 = ks * 8;
        uint32_t a[2][4], b[4][2];
#pragma unroll
        for (int mt = 0; mt < 2; ++mt) {
            int r = wm + mt * 16 + qrow;
            uint2 lo = *(const uint2*)&Asu[r * SST + k0 + 2 * qcol];
            uint2 hi = *(const uint2*)&Asu[(r + 8) * SST + k0 + 2 * qcol];
            a[mt][0] = lo.x; a[mt][1] = hi.x; a[mt][2] = lo.y; a[mt][3] = hi.y;
        }
#pragma unroll
        for (int nt = 0; nt < 4; ++nt) {
            int n = wn + nt * 8 + qrow;
            uint2 bb = *(const uint2*)&Bsu[n * SST + k0 + 2 * qcol];
            b[nt][0] = bb.x; b[nt][1] = bb.y;
        }
#pragma unroll
        for (int mt = 0; mt < 2; ++mt)
#pragma unroll
            for (int nt = 0; nt < 4; ++nt)
                mma_tf32(c[mt][nt], a[mt], b[nt]);
    }

    __syncthreads();
#pragma unroll
    for (int mt = 0; mt < 2; ++mt) {
        int r = wm + mt * 16 + qrow;
#pragma unroll
        for (int nt = 0; nt < 4; ++nt) {
            int cc = wn + nt * 8 + qcol * 2;
            *(float2*)&As[r * SST + cc] = make_float2(c[mt][nt][0], c[mt][nt][1]);
            *(float2*)&As[(r + 8) * SST + cc] = make_float2(c[mt][nt][2], c[mt][nt][3]);
        }
    }
    __syncthreads();

    // epilogue: warp w owns rows w*8..w*8+7 (matches gather mapping)
    float4 bv = *(const float4*)(s_b + colb);
    float4 gv = *(const float4*)(s_g + colb);
    float4 bev = *(const float4*)(s_be + colb);
#pragma unroll
    for (int rr = 0; rr < 8; ++rr) {
        int r = wid * 8 + rr;
        int row = m0 + r;
        if (row >= NN) break;
        float4 d = *(const float4*)&As[r * SST + colb];
        d.x += bv.x; d.y += bv.y; d.z += bv.z; d.w += bv.w;
        float s1 = d.x + d.y + d.z + d.w;
#pragma unroll
        for (int o = 16; o; o >>= 1) s1 += __shfl_xor_sync(0xffffffffu, s1, o);
        float mu = s1 * (1.f / 128.f);
        float d0 = d.x - mu, d1 = d.y - mu, d2 = d.z - mu, d3 = d.w - mu;
        float s2 = d0 * d0 + d1 * d1 + d2 * d2 + d3 * d3;
#pragma unroll
        for (int o = 16; o; o >>= 1) s2 += __shfl_xor_sync(0xffffffffu, s2, o);
        float rs = rsqrtf(s2 * (1.f / 128.f) + 1e-5f);

        float4 xv = *(const float4*)(xin + (size_t)row * DD + colb);  // residual (L2-hot)
        float v0 = d0 * rs * gv.x + bev.x + xv.x;
        float v1 = d1 * rs * gv.y + bev.y + xv.y;
        float v2 = d2 * rs * gv.z + bev.z + xv.z;
        float v3 = d3 * rs * gv.w + bev.w + xv.w;
        v0 = v0 / (1.f + __expf(-v0));
        v1 = v1 / (1.f + __expf(-v1));
        v2 = v2 / (1.f + __expf(-v2));
        v3 = v3 / (1.f + __expf(-v3));
        *(float4*)(y + (size_t)row * DD + colb) = make_float4(v0, v1, v2, v3);
    }
}

// ======================= global mean pool =======================
__device__ __forceinline__ int lowerb(const int* __restrict__ a, int n, int key) {
    int lo = 0, hi = n;
    while (lo < hi) {
        int mid = (lo + hi) >> 1;
        if (a[mid] < key) lo = mid + 1; else hi = mid;
    }
    return lo;
}
__global__ void __launch_bounds__(512) k_pool(const float* __restrict__ x,
                                              const int* __restrict__ batch,
                                              float* __restrict__ out) {
    __shared__ int sl, sh;
    __shared__ float part[4][128];
    int g = blockIdx.x;
    if (threadIdx.x == 0) {
        sl = lowerb(batch, NN, g);
        sh = lowerb(batch, NN, g + 1);
    }
    __syncthreads();
    int lo = sl, hi = sh;
    int c = threadIdx.x & 127;
    int rchunk = threadIdx.x >> 7;   // 0..3
    float sum = 0.f;
    for (int n = lo + rchunk; n < hi; n += 4) sum += x[(size_t)n * DD + c];
    part[rchunk][c] = sum;
    __syncthreads();
    if (rchunk == 0) {
        float t = part[0][c] + part[1][c] + part[2][c] + part[3][c];
        out[g * DD + c] = t / fmaxf((float)(hi - lo), 1.f);
    }
}

// ======================= launch =======================
extern "C" void kernel_launch(void* const* d_in, const int* in_sizes, int n_in,
                              void* d_out, int out_size) {
    const float* x     = (const float*)d_in[0];
    const int*   ei    = (const int*)d_in[1];
    const int*   batch = (const int*)d_in[2];
    const float* W[3]  = {(const float*)d_in[3],  (const float*)d_in[7],  (const float*)d_in[11]};
    const float* b[3]  = {(const float*)d_in[4],  (const float*)d_in[8],  (const float*)d_in[12]};
    const float* g[3]  = {(const float*)d_in[5],  (const float*)d_in[9],  (const float*)d_in[13]};
    const float* be[3] = {(const float*)d_in[6],  (const float*)d_in[10], (const float*)d_in[14]};
    float* out = (float*)d_out;

    float *y0 = nullptr, *y1 = nullptr;
    uint32_t* wt = nullptr;
    cudaGetSymbolAddress((void**)&y0, g_y0);
    cudaGetSymbolAddress((void**)&y1, g_y1);
    cudaGetSymbolAddress((void**)&wt, g_wt);

    cudaFuncSetAttribute(k_layer, cudaFuncAttributeMaxDynamicSharedMemorySize, DYN_SMEM);

    k_init<<<(NN + 255) / 256, 256>>>();
    k_deg<<<(EE / 4 + 255) / 256, 256>>>(ei);
    k_scan<<<1, 1024>>>();
    k_fill<<<(EE + 255) / 256, 256>>>(ei);
    dim3 wtg((DD * DD + 255) / 256, 3);
    k_wt<<<wtg, 256>>>(W[0], W[1], W[2]);

    const int layer_blocks = (NN + TILE_M - 1) / TILE_M;
    k_layer<<<layer_blocks, 256, DYN_SMEM>>>(x,  wt + 0 * DD * DD, b[0], g[0], be[0], y0);
    k_layer<<<layer_blocks, 256, DYN_SMEM>>>(y0, wt + 1 * DD * DD, b[1], g[1], be[1], y1);
    k_layer<<<layer_blocks, 256, DYN_SMEM>>>(y1, wt + 2 * DD * DD, b[2], g[2], be[2], y0);

    k_pool<<<GG, 512>>>(y0, batch, out);
}

// round 6
// speedup vs baseline: 1.2338x; 1.2338x over previous
#include <cuda_runtime.h>
#include <cstdint>
#include <math.h>

#define NN 50000
#define EE 600000
#define DD 128
#define GG 128

// ---------------- device scratch ----------------
__device__ float g_xa[NN * DD];
__device__ float g_y0[NN * DD];
__device__ float g_y1[NN * DD];
__device__ int   g_deg[NN];
__device__ int   g_rank[EE];
__device__ float g_dinv[NN];
__device__ int   g_rowptr[NN + 1];
__device__ int   g_csrc[EE];
__device__ float g_cw[EE];
__device__ uint32_t g_wt[3][DD * DD];   // W^T, tf32 bits, permuted k-layout

__device__ __forceinline__ uint32_t f2tf32(float f) {
    uint32_t r;
    asm("cvt.rna.tf32.f32 %0, %1;" : "=r"(r) : "f"(f));
    return r;
}

__device__ __forceinline__ void mma_tf32(float c[4], const uint32_t a[4], const uint32_t b[2]) {
    asm volatile(
        "mma.sync.aligned.m16n8k8.row.col.f32.tf32.tf32.f32 "
        "{%0,%1,%2,%3}, {%4,%5,%6,%7}, {%8,%9}, {%0,%1,%2,%3};"
        : "+f"(c[0]), "+f"(c[1]), "+f"(c[2]), "+f"(c[3])
        : "r"(a[0]), "r"(a[1]), "r"(a[2]), "r"(a[3]), "r"(b[0]), "r"(b[1]));
}

// permute within 8-col group so (k, k+4) are adjacent: c -> (c&3)*2 + (c>>2)
__device__ __forceinline__ int kperm(int c) { return ((c & 3) << 1) | ((c >> 2) & 1); }

// ======================= CSR build =======================
__global__ void k_init() {
    int i = blockIdx.x * blockDim.x + threadIdx.x;
    if (i < NN) g_deg[i] = 0;
}
// degree + per-edge rank (removes atomics from k_fill)
__global__ void k_deg(const int* __restrict__ ei) {
    int e = blockIdx.x * blockDim.x + threadIdx.x;
    if (e < EE) g_rank[e] = atomicAdd(&g_deg[ei[EE + e]], 1);
}
// block 0: exclusive scan + dinv; blocks 1..3: W^T tf32 permuted precompute
__global__ void k_scan_wt(const float* __restrict__ W0, const float* __restrict__ W1,
                          const float* __restrict__ W2) {
    if (blockIdx.x > 0) {
        const float* Ws[3] = {W0, W1, W2};
        int l = blockIdx.x - 1;
        for (int i = threadIdx.x; i < DD * DD; i += 1024) {
            int n = i >> 7;
            int kp = i & 127;
            int k = (kp & ~7) + ((kp & 7) >> 1) + ((kp & 1) << 2);  // inverse perm
            g_wt[l][i] = f2tf32(Ws[l][(size_t)k * DD + n]);
        }
        return;
    }
    const int CH = (NN + 1023) / 1024;
    __shared__ int ss[1024];
    int t = threadIdx.x;
    int vals[CH];
    int base = t * CH;
    int loc = 0;
#pragma unroll
    for (int i = 0; i < CH; ++i) {
        int idx = base + i;
        int v = (idx < NN) ? g_deg[idx] : 0;
        if (idx < NN) g_dinv[idx] = rsqrtf((float)(v + 1));
        vals[i] = loc;
        loc += v;
    }
    ss[t] = loc;
    __syncthreads();
    for (int off = 1; off < 1024; off <<= 1) {
        int v = (t >= off) ? ss[t - off] : 0;
        __syncthreads();
        ss[t] += v;
        __syncthreads();
    }
    int pre = (t > 0) ? ss[t - 1] : 0;
#pragma unroll
    for (int i = 0; i < CH; ++i) {
        int idx = base + i;
        if (idx < NN) g_rowptr[idx] = pre + vals[i];
    }
    if (t == 1023) g_rowptr[NN] = ss[1023];
}
// atomic-free CSR fill using precomputed ranks
__global__ void k_fill(const int* __restrict__ ei) {
    int e = blockIdx.x * blockDim.x + threadIdx.x;
    if (e < EE) {
        int s = ei[e];
        int d = ei[EE + e];
        int pos = g_rowptr[d] + g_rank[e];
        g_csrc[pos] = s;
        g_cw[pos] = g_dinv[s] * g_dinv[d];
    }
}

// ======================= aggregation: xa = A_norm @ x =======================
// one warp per node; 4 independent accumulators for MLP=4
__global__ void __launch_bounds__(256) k_agg(const float* __restrict__ xin,
                                             float* __restrict__ y) {
    int w = (blockIdx.x * blockDim.x + threadIdx.x) >> 5;
    int lane = threadIdx.x & 31;
    if (w >= NN) return;
    int col = lane * 4;

    float di = g_dinv[w];
    float sw = di * di;
    float4 a0 = *(const float4*)(xin + (size_t)w * DD + col);
    a0.x *= sw; a0.y *= sw; a0.z *= sw; a0.w *= sw;
    float4 a1 = make_float4(0.f, 0.f, 0.f, 0.f);
    float4 a2 = make_float4(0.f, 0.f, 0.f, 0.f);
    float4 a3 = make_float4(0.f, 0.f, 0.f, 0.f);

    int e0 = g_rowptr[w], e1 = g_rowptr[w + 1];
    int e = e0;
    for (; e + 4 <= e1; e += 4) {
        int s0 = __ldg(&g_csrc[e + 0]);
        int s1 = __ldg(&g_csrc[e + 1]);
        int s2 = __ldg(&g_csrc[e + 2]);
        int s3 = __ldg(&g_csrc[e + 3]);
        float w0 = __ldg(&g_cw[e + 0]);
        float w1 = __ldg(&g_cw[e + 1]);
        float w2 = __ldg(&g_cw[e + 2]);
        float w3 = __ldg(&g_cw[e + 3]);
        float4 h0 = *(const float4*)(xin + (size_t)s0 * DD + col);
        float4 h1 = *(const float4*)(xin + (size_t)s1 * DD + col);
        float4 h2 = *(const float4*)(xin + (size_t)s2 * DD + col);
        float4 h3 = *(const float4*)(xin + (size_t)s3 * DD + col);
        a0.x += w0 * h0.x; a0.y += w0 * h0.y; a0.z += w0 * h0.z; a0.w += w0 * h0.w;
        a1.x += w1 * h1.x; a1.y += w1 * h1.y; a1.z += w1 * h1.z; a1.w += w1 * h1.w;
        a2.x += w2 * h2.x; a2.y += w2 * h2.y; a2.z += w2 * h2.z; a2.w += w2 * h2.w;
        a3.x += w3 * h3.x; a3.y += w3 * h3.y; a3.z += w3 * h3.z; a3.w += w3 * h3.w;
    }
    for (; e < e1; ++e) {
        int s = __ldg(&g_csrc[e]);
        float wt = __ldg(&g_cw[e]);
        float4 hs = *(const float4*)(xin + (size_t)s * DD + col);
        a0.x += wt * hs.x; a0.y += wt * hs.y; a0.z += wt * hs.z; a0.w += wt * hs.w;
    }
    a0.x += a1.x + a2.x + a3.x;
    a0.y += a1.y + a2.y + a3.y;
    a0.z += a1.z + a2.z + a3.z;
    a0.w += a1.w + a2.w + a3.w;
    *(float4*)(y + (size_t)w * DD + col) = a0;
}

// ======================= fused tf32 mma.sync GEMM + epilogue (R4) =======================
#define TILE_M 64
#define SST 132
#define DYN_SMEM ((TILE_M + 128) * SST * 4)

__global__ void __launch_bounds__(256) k_gemm_fused(
    const float* __restrict__ A, const uint32_t* __restrict__ Wt,
    const float* __restrict__ bias, const float* __restrict__ gamma,
    const float* __restrict__ beta, const float* __restrict__ xres,
    float* __restrict__ y) {
    extern __shared__ float smem[];
    float* As = smem;
    float* Bs = smem + TILE_M * SST;
    uint32_t* Asu = (uint32_t*)As;
    uint32_t* Bsu = (uint32_t*)Bs;
    __shared__ float s_b[128], s_g[128], s_be[128];

    int tid = threadIdx.x;
    int wid = tid >> 5;
    int lane = tid & 31;
    int m0 = blockIdx.x * TILE_M;

    if (tid < 128) { s_b[tid] = bias[tid]; s_g[tid] = gamma[tid]; s_be[tid] = beta[tid]; }

    for (int i = tid; i < TILE_M * 32; i += 256) {
        int m = i >> 5;
        int c = (i & 31) << 2;
        int gm = m0 + m;
        float4 v = (gm < NN) ? *(const float4*)(A + (size_t)gm * DD + c)
                             : make_float4(0.f, 0.f, 0.f, 0.f);
        uint32_t t0 = f2tf32(v.x), t1 = f2tf32(v.y), t2 = f2tf32(v.z), t3 = f2tf32(v.w);
        int base = m * SST + (c & ~7);
        int g0 = c & 7;
        Asu[base + kperm(g0 + 0)] = t0;
        Asu[base + kperm(g0 + 1)] = t1;
        Asu[base + kperm(g0 + 2)] = t2;
        Asu[base + kperm(g0 + 3)] = t3;
    }
    for (int i = tid; i < 128 * 32; i += 256) {
        int n = i >> 5;
        int c4 = (i & 31) << 2;
        *(uint4*)&Bsu[n * SST + c4] = *(const uint4*)&Wt[n * DD + c4];
    }
    __syncthreads();

    const int wm = (wid >> 2) * 32;
    const int wn = (wid & 3) * 32;
    const int qrow = lane >> 2;
    const int qcol = lane & 3;

    float c[2][4][4];
#pragma unroll
    for (int mt = 0; mt < 2; ++mt)
#pragma unroll
        for (int nt = 0; nt < 4; ++nt)
#pragma unroll
            for (int j = 0; j < 4; ++j) c[mt][nt][j] = 0.f;

#pragma unroll
    for (int ks = 0; ks < 16; ++ks) {
        int k0 = ks * 8;
        uint32_t a[2][4], b[4][2];
#pragma unroll
        for (int mt = 0; mt < 2; ++mt) {
            int r = wm + mt * 16 + qrow;
            uint2 lo = *(const uint2*)&Asu[r * SST + k0 + 2 * qcol];
            uint2 hi = *(const uint2*)&Asu[(r + 8) * SST + k0 + 2 * qcol];
            a[mt][0] = lo.x; a[mt][1] = hi.x; a[mt][2] = lo.y; a[mt][3] = hi.y;
        }
#pragma unroll
        for (int nt = 0; nt < 4; ++nt) {
            int n = wn + nt * 8 + qrow;
            uint2 bb = *(const uint2*)&Bsu[n * SST + k0 + 2 * qcol];
            b[nt][0] = bb.x; b[nt][1] = bb.y;
        }
#pragma unroll
        for (int mt = 0; mt < 2; ++mt)
#pragma unroll
            for (int nt = 0; nt < 4; ++nt)
                mma_tf32(c[mt][nt], a[mt], b[nt]);
    }

    __syncthreads();
#pragma unroll
    for (int mt = 0; mt < 2; ++mt) {
        int r = wm + mt * 16 + qrow;
#pragma unroll
        for (int nt = 0; nt < 4; ++nt) {
            int cc = wn + nt * 8 + qcol * 2;
            *(float2*)&As[r * SST + cc] = make_float2(c[mt][nt][0], c[mt][nt][1]);
            *(float2*)&As[(r + 8) * SST + cc] = make_float2(c[mt][nt][2], c[mt][nt][3]);
        }
    }
    __syncthreads();

    int colb = lane * 4;
    float4 bv = *(const float4*)(s_b + colb);
    float4 gv = *(const float4*)(s_g + colb);
    float4 bev = *(const float4*)(s_be + colb);
#pragma unroll
    for (int rr = 0; rr < 8; ++rr) {
        int r = wid * 8 + rr;
        int row = m0 + r;
        if (row >= NN) break;
        float4 d = *(const float4*)&As[r * SST + colb];
        d.x += bv.x; d.y += bv.y; d.z += bv.z; d.w += bv.w;
        float s1 = d.x + d.y + d.z + d.w;
#pragma unroll
        for (int o = 16; o; o >>= 1) s1 += __shfl_xor_sync(0xffffffffu, s1, o);
        float mu = s1 * (1.f / 128.f);
        float d0 = d.x - mu, d1 = d.y - mu, d2 = d.z - mu, d3 = d.w - mu;
        float s2 = d0 * d0 + d1 * d1 + d2 * d2 + d3 * d3;
#pragma unroll
        for (int o = 16; o; o >>= 1) s2 += __shfl_xor_sync(0xffffffffu, s2, o);
        float rs = rsqrtf(s2 * (1.f / 128.f) + 1e-5f);

        float4 xv = *(const float4*)(xres + (size_t)row * DD + colb);
        float v0 = d0 * rs * gv.x + bev.x + xv.x;
        float v1 = d1 * rs * gv.y + bev.y + xv.y;
        float v2 = d2 * rs * gv.z + bev.z + xv.z;
        float v3 = d3 * rs * gv.w + bev.w + xv.w;
        v0 = v0 / (1.f + __expf(-v0));
        v1 = v1 / (1.f + __expf(-v1));
        v2 = v2 / (1.f + __expf(-v2));
        v3 = v3 / (1.f + __expf(-v3));
        *(float4*)(y + (size_t)row * DD + colb) = make_float4(v0, v1, v2, v3);
    }
}

// ======================= global mean pool =======================
__device__ __forceinline__ int lowerb(const int* __restrict__ a, int n, int key) {
    int lo = 0, hi = n;
    while (lo < hi) {
        int mid = (lo + hi) >> 1;
        if (a[mid] < key) lo = mid + 1; else hi = mid;
    }
    return lo;
}
__global__ void __launch_bounds__(512) k_pool(const float* __restrict__ x,
                                              const int* __restrict__ batch,
                                              float* __restrict__ out) {
    __shared__ int sl, sh;
    __shared__ float part[4][128];
    int g = blockIdx.x;
    if (threadIdx.x == 0) {
        sl = lowerb(batch, NN, g);
        sh = lowerb(batch, NN, g + 1);
    }
    __syncthreads();
    int lo = sl, hi = sh;
    int c = threadIdx.x & 127;
    int rchunk = threadIdx.x >> 7;
    float sum = 0.f;
    for (int n = lo + rchunk; n < hi; n += 4) sum += x[(size_t)n * DD + c];
    part[rchunk][c] = sum;
    __syncthreads();
    if (rchunk == 0) {
        float t = part[0][c] + part[1][c] + part[2][c] + part[3][c];
        out[g * DD + c] = t / fmaxf((float)(hi - lo), 1.f);
    }
}

// ======================= launch =======================
extern "C" void kernel_launch(void* const* d_in, const int* in_sizes, int n_in,
                              void* d_out, int out_size) {
    const float* x     = (const float*)d_in[0];
    const int*   ei    = (const int*)d_in[1];
    const int*   batch = (const int*)d_in[2];
    const float* W[3]  = {(const float*)d_in[3],  (const float*)d_in[7],  (const float*)d_in[11]};
    const float* b[3]  = {(const float*)d_in[4],  (const float*)d_in[8],  (const float*)d_in[12]};
    const float* g[3]  = {(const float*)d_in[5],  (const float*)d_in[9],  (const float*)d_in[13]};
    const float* be[3] = {(const float*)d_in[6],  (const float*)d_in[10], (const float*)d_in[14]};
    float* out = (float*)d_out;

    float *xa = nullptr, *y0 = nullptr, *y1 = nullptr;
    uint32_t* wt = nullptr;
    cudaGetSymbolAddress((void**)&xa, g_xa);
    cudaGetSymbolAddress((void**)&y0, g_y0);
    cudaGetSymbolAddress((void**)&y1, g_y1);
    cudaGetSymbolAddress((void**)&wt, g_wt);

    cudaFuncSetAttribute(k_gemm_fused, cudaFuncAttributeMaxDynamicSharedMemorySize, DYN_SMEM);

    k_init<<<(NN + 255) / 256, 256>>>();
    k_deg<<<(EE + 255) / 256, 256>>>(ei);
    k_scan_wt<<<4, 1024>>>(W[0], W[1], W[2]);
    k_fill<<<(EE + 255) / 256, 256>>>(ei);

    const int agg_blocks = (NN * 32 + 255) / 256;
    const int gemm_blocks = (NN + TILE_M - 1) / TILE_M;

    k_agg<<<agg_blocks, 256>>>(x, xa);
    k_gemm_fused<<<gemm_blocks, 256, DYN_SMEM>>>(xa, wt + 0 * DD * DD, b[0], g[0], be[0], x, y0);
    k_agg<<<agg_blocks, 256>>>(y0, xa);
    k_gemm_fused<<<gemm_blocks, 256, DYN_SMEM>>>(xa, wt + 1 * DD * DD, b[1], g[1], be[1], y0, y1);
    k_agg<<<agg_blocks, 256>>>(y1, xa);
    k_gemm_fused<<<gemm_blocks, 256, DYN_SMEM>>>(xa, wt + 2 * DD * DD, b[2], g[2], be[2], y1, y0);

    k_pool<<<GG, 512>>>(y0, batch, out);
}

// round 7
// speedup vs baseline: 1.2814x; 1.0386x over previous
#include <cuda_runtime.h>
#include <cuda_fp16.h>
#include <cstdint>
#include <math.h>

#define NN 50000
#define EE 600000
#define DD 128
#define GG 128

// ---------------- device scratch ----------------
__device__ __half g_a16[NN * DD];      // activation (gather source), fp16
__device__ __half g_xa16[NN * DD];     // aggregated output, fp16
__device__ float  g_y0[NN * DD];       // layer output ping (fp32, residual/pool)
__device__ float  g_y1[NN * DD];       // layer output pong
__device__ int    g_deg[NN];
__device__ int    g_rank[EE];
__device__ float  g_dinv[NN];
__device__ int    g_rowptr[NN + 1];
__device__ int    g_csrc[EE];
__device__ float  g_cw[EE];
__device__ uint32_t g_wt[3][DD * DD];  // W^T, tf32 bits, permuted k-layout

__device__ __forceinline__ uint32_t f2tf32(float f) {
    uint32_t r;
    asm("cvt.rna.tf32.f32 %0, %1;" : "=r"(r) : "f"(f));
    return r;
}

__device__ __forceinline__ void mma_tf32(float c[4], const uint32_t a[4], const uint32_t b[2]) {
    asm volatile(
        "mma.sync.aligned.m16n8k8.row.col.f32.tf32.tf32.f32 "
        "{%0,%1,%2,%3}, {%4,%5,%6,%7}, {%8,%9}, {%0,%1,%2,%3};"
        : "+f"(c[0]), "+f"(c[1]), "+f"(c[2]), "+f"(c[3])
        : "r"(a[0]), "r"(a[1]), "r"(a[2]), "r"(a[3]), "r"(b[0]), "r"(b[1]));
}

// permute within 8-col group so (k, k+4) are adjacent: c -> (c&3)*2 + (c>>2)
__device__ __forceinline__ int kperm(int c) { return ((c & 3) << 1) | ((c >> 2) & 1); }

// ======================= deg + x->fp16 convert (one kernel) =======================
#define DEGB ((EE + 255) / 256)           // 2344
#define CVTB ((NN * DD / 8 + 255) / 256)  // 3125

__global__ void k_deg_x16(const int* __restrict__ ei, const float* __restrict__ x) {
    if (blockIdx.x < DEGB) {
        int e = blockIdx.x * 256 + threadIdx.x;
        if (e < EE) g_rank[e] = atomicAdd(&g_deg[ei[EE + e]], 1);
    } else {
        int i = (blockIdx.x - DEGB) * 256 + threadIdx.x;   // 8 floats per thread
        if (i < NN * DD / 8) {
            float4 v0 = *(const float4*)(x + (size_t)i * 8);
            float4 v1 = *(const float4*)(x + (size_t)i * 8 + 4);
            __half2 h0 = __floats2half2_rn(v0.x, v0.y);
            __half2 h1 = __floats2half2_rn(v0.z, v0.w);
            __half2 h2 = __floats2half2_rn(v1.x, v1.y);
            __half2 h3 = __floats2half2_rn(v1.z, v1.w);
            uint4 o;
            o.x = *(uint32_t*)&h0; o.y = *(uint32_t*)&h1;
            o.z = *(uint32_t*)&h2; o.w = *(uint32_t*)&h3;
            *(uint4*)(g_a16 + (size_t)i * 8) = o;
        }
    }
}

// ======================= scan + dinv + W^T precompute =======================
__global__ void k_scan_wt(const float* __restrict__ W0, const float* __restrict__ W1,
                          const float* __restrict__ W2) {
    if (blockIdx.x > 0) {
        const float* Ws[3] = {W0, W1, W2};
        int l = blockIdx.x - 1;
        for (int i = threadIdx.x; i < DD * DD; i += 1024) {
            int n = i >> 7;
            int kp = i & 127;
            int k = (kp & ~7) + ((kp & 7) >> 1) + ((kp & 1) << 2);  // inverse perm
            g_wt[l][i] = f2tf32(Ws[l][(size_t)k * DD + n]);
        }
        return;
    }
    const int CH = (NN + 1023) / 1024;
    __shared__ int ss[1024];
    int t = threadIdx.x;
    int vals[CH];
    int base = t * CH;
    int loc = 0;
#pragma unroll
    for (int i = 0; i < CH; ++i) {
        int idx = base + i;
        int v = (idx < NN) ? g_deg[idx] : 0;
        if (idx < NN) g_dinv[idx] = rsqrtf((float)(v + 1));
        vals[i] = loc;
        loc += v;
    }
    ss[t] = loc;
    __syncthreads();
    for (int off = 1; off < 1024; off <<= 1) {
        int v = (t >= off) ? ss[t - off] : 0;
        __syncthreads();
        ss[t] += v;
        __syncthreads();
    }
    int pre = (t > 0) ? ss[t - 1] : 0;
#pragma unroll
    for (int i = 0; i < CH; ++i) {
        int idx = base + i;
        if (idx < NN) g_rowptr[idx] = pre + vals[i];
    }
    if (t == 1023) g_rowptr[NN] = ss[1023];
}

// atomic-free CSR fill using precomputed ranks
__global__ void k_fill(const int* __restrict__ ei) {
    int e = blockIdx.x * blockDim.x + threadIdx.x;
    if (e < EE) {
        int s = ei[e];
        int d = ei[EE + e];
        int pos = g_rowptr[d] + g_rank[e];
        g_csrc[pos] = s;
        g_cw[pos] = g_dinv[s] * g_dinv[d];
    }
}

// ======================= aggregation (fp16 gather): xa16 = A_norm @ a16 =======================
__device__ __forceinline__ float4 h4tof4(uint2 raw) {
    __half2 h0 = *(__half2*)&raw.x;
    __half2 h1 = *(__half2*)&raw.y;
    float2 f0 = __half22float2(h0);
    float2 f1 = __half22float2(h1);
    return make_float4(f0.x, f0.y, f1.x, f1.y);
}

__global__ void __launch_bounds__(256) k_agg(const __half* __restrict__ a16,
                                             __half* __restrict__ xa16) {
    int w = (blockIdx.x * blockDim.x + threadIdx.x) >> 5;
    int lane = threadIdx.x & 31;
    if (w >= NN) return;
    int col = lane * 4;

    float di = g_dinv[w];
    float sw = di * di;
    float4 a0 = h4tof4(*(const uint2*)(a16 + (size_t)w * DD + col));
    a0.x *= sw; a0.y *= sw; a0.z *= sw; a0.w *= sw;
    float4 a1 = make_float4(0.f, 0.f, 0.f, 0.f);
    float4 a2 = make_float4(0.f, 0.f, 0.f, 0.f);
    float4 a3 = make_float4(0.f, 0.f, 0.f, 0.f);

    int e0 = g_rowptr[w], e1 = g_rowptr[w + 1];
    int e = e0;
    for (; e + 4 <= e1; e += 4) {
        int s0 = __ldg(&g_csrc[e + 0]);
        int s1 = __ldg(&g_csrc[e + 1]);
        int s2 = __ldg(&g_csrc[e + 2]);
        int s3 = __ldg(&g_csrc[e + 3]);
        float w0 = __ldg(&g_cw[e + 0]);
        float w1 = __ldg(&g_cw[e + 1]);
        float w2 = __ldg(&g_cw[e + 2]);
        float w3 = __ldg(&g_cw[e + 3]);
        float4 h0 = h4tof4(*(const uint2*)(a16 + (size_t)s0 * DD + col));
        float4 h1 = h4tof4(*(const uint2*)(a16 + (size_t)s1 * DD + col));
        float4 h2 = h4tof4(*(const uint2*)(a16 + (size_t)s2 * DD + col));
        float4 h3 = h4tof4(*(const uint2*)(a16 + (size_t)s3 * DD + col));
        a0.x += w0 * h0.x; a0.y += w0 * h0.y; a0.z += w0 * h0.z; a0.w += w0 * h0.w;
        a1.x += w1 * h1.x; a1.y += w1 * h1.y; a1.z += w1 * h1.z; a1.w += w1 * h1.w;
        a2.x += w2 * h2.x; a2.y += w2 * h2.y; a2.z += w2 * h2.z; a2.w += w2 * h2.w;
        a3.x += w3 * h3.x; a3.y += w3 * h3.y; a3.z += w3 * h3.z; a3.w += w3 * h3.w;
    }
    for (; e < e1; ++e) {
        int s = __ldg(&g_csrc[e]);
        float wt = __ldg(&g_cw[e]);
        float4 hs = h4tof4(*(const uint2*)(a16 + (size_t)s * DD + col));
        a0.x += wt * hs.x; a0.y += wt * hs.y; a0.z += wt * hs.z; a0.w += wt * hs.w;
    }
    a0.x += a1.x + a2.x + a3.x;
    a0.y += a1.y + a2.y + a3.y;
    a0.z += a1.z + a2.z + a3.z;
    a0.w += a1.w + a2.w + a3.w;

    __half2 p0 = __floats2half2_rn(a0.x, a0.y);
    __half2 p1 = __floats2half2_rn(a0.z, a0.w);
    uint2 st;
    st.x = *(uint32_t*)&p0;
    st.y = *(uint32_t*)&p1;
    *(uint2*)(xa16 + (size_t)w * DD + col) = st;
}

// ======================= fused tf32 mma.sync GEMM + epilogue =======================
#define TILE_M 64
#define SST 132
#define DYN_SMEM ((TILE_M + 128) * SST * 4)

__global__ void __launch_bounds__(256) k_gemm_fused(
    const __half* __restrict__ A16, const uint32_t* __restrict__ Wt,
    const float* __restrict__ bias, const float* __restrict__ gamma,
    const float* __restrict__ beta, const float* __restrict__ xres,
    float* __restrict__ y, __half* __restrict__ y16) {
    extern __shared__ float smem[];
    float* As = smem;
    float* Bs = smem + TILE_M * SST;
    uint32_t* Asu = (uint32_t*)As;
    uint32_t* Bsu = (uint32_t*)Bs;
    __shared__ float s_b[128], s_g[128], s_be[128];

    int tid = threadIdx.x;
    int wid = tid >> 5;
    int lane = tid & 31;
    int m0 = blockIdx.x * TILE_M;

    if (tid < 128) { s_b[tid] = bias[tid]; s_g[tid] = gamma[tid]; s_be[tid] = beta[tid]; }

    // A tile from fp16 (exact fp16->tf32), permuted-k store
    for (int i = tid; i < TILE_M * 16; i += 256) {
        int m = i >> 4;
        int c = (i & 15) << 3;           // 8-col group
        int gm = m0 + m;
        uint4 raw = (gm < NN) ? *(const uint4*)(A16 + (size_t)gm * DD + c)
                              : make_uint4(0, 0, 0, 0);
        float4 f0 = h4tof4(make_uint2(raw.x, raw.y));
        float4 f1 = h4tof4(make_uint2(raw.z, raw.w));
        float f[8] = {f0.x, f0.y, f0.z, f0.w, f1.x, f1.y, f1.z, f1.w};
        int base = m * SST + c;
#pragma unroll
        for (int j = 0; j < 8; ++j)
            Asu[base + (((j & 3) << 1) | (j >> 2))] = f2tf32(f[j]);
    }
    for (int i = tid; i < 128 * 32; i += 256) {
        int n = i >> 5;
        int c4 = (i & 31) << 2;
        *(uint4*)&Bsu[n * SST + c4] = *(const uint4*)&Wt[n * DD + c4];
    }
    __syncthreads();

    const int wm = (wid >> 2) * 32;
    const int wn = (wid & 3) * 32;
    const int qrow = lane >> 2;
    const int qcol = lane & 3;

    float c[2][4][4];
#pragma unroll
    for (int mt = 0; mt < 2; ++mt)
#pragma unroll
        for (int nt = 0; nt < 4; ++nt)
#pragma unroll
            for (int j = 0; j < 4; ++j) c[mt][nt][j] = 0.f;

#pragma unroll
    for (int ks = 0; ks < 16; ++ks) {
        int k0 = ks * 8;
        uint32_t a[2][4], b[4][2];
#pragma unroll
        for (int mt = 0; mt < 2; ++mt) {
            int r = wm + mt * 16 + qrow;
            uint2 lo = *(const uint2*)&Asu[r * SST + k0 + 2 * qcol];
            uint2 hi = *(const uint2*)&Asu[(r + 8) * SST + k0 + 2 * qcol];
            a[mt][0] = lo.x; a[mt][1] = hi.x; a[mt][2] = lo.y; a[mt][3] = hi.y;
        }
#pragma unroll
        for (int nt = 0; nt < 4; ++nt) {
            int n = wn + nt * 8 + qrow;
            uint2 bb = *(const uint2*)&Bsu[n * SST + k0 + 2 * qcol];
            b[nt][0] = bb.x; b[nt][1] = bb.y;
        }
#pragma unroll
        for (int mt = 0; mt < 2; ++mt)
#pragma unroll
            for (int nt = 0; nt < 4; ++nt)
                mma_tf32(c[mt][nt], a[mt], b[nt]);
    }

    __syncthreads();
#pragma unroll
    for (int mt = 0; mt < 2; ++mt) {
        int r = wm + mt * 16 + qrow;
#pragma unroll
        for (int nt = 0; nt < 4; ++nt) {
            int cc = wn + nt * 8 + qcol * 2;
            *(float2*)&As[r * SST + cc] = make_float2(c[mt][nt][0], c[mt][nt][1]);
            *(float2*)&As[(r + 8) * SST + cc] = make_float2(c[mt][nt][2], c[mt][nt][3]);
        }
    }
    __syncthreads();

    int colb = lane * 4;
    float4 bv = *(const float4*)(s_b + colb);
    float4 gv = *(const float4*)(s_g + colb);
    float4 bev = *(const float4*)(s_be + colb);
#pragma unroll
    for (int rr = 0; rr < 8; ++rr) {
        int r = wid * 8 + rr;
        int row = m0 + r;
        if (row >= NN) break;
        float4 d = *(const float4*)&As[r * SST + colb];
        d.x += bv.x; d.y += bv.y; d.z += bv.z; d.w += bv.w;
        float s1 = d.x + d.y + d.z + d.w;
#pragma unroll
        for (int o = 16; o; o >>= 1) s1 += __shfl_xor_sync(0xffffffffu, s1, o);
        float mu = s1 * (1.f / 128.f);
        float d0 = d.x - mu, d1 = d.y - mu, d2 = d.z - mu, d3 = d.w - mu;
        float s2 = d0 * d0 + d1 * d1 + d2 * d2 + d3 * d3;
#pragma unroll
        for (int o = 16; o; o >>= 1) s2 += __shfl_xor_sync(0xffffffffu, s2, o);
        float rs = rsqrtf(s2 * (1.f / 128.f) + 1e-5f);

        float4 xv = *(const float4*)(xres + (size_t)row * DD + colb);
        float v0 = d0 * rs * gv.x + bev.x + xv.x;
        float v1 = d1 * rs * gv.y + bev.y + xv.y;
        float v2 = d2 * rs * gv.z + bev.z + xv.z;
        float v3 = d3 * rs * gv.w + bev.w + xv.w;
        v0 = v0 / (1.f + __expf(-v0));
        v1 = v1 / (1.f + __expf(-v1));
        v2 = v2 / (1.f + __expf(-v2));
        v3 = v3 / (1.f + __expf(-v3));
        *(float4*)(y + (size_t)row * DD + colb) = make_float4(v0, v1, v2, v3);
        __half2 p0 = __floats2half2_rn(v0, v1);
        __half2 p1 = __floats2half2_rn(v2, v3);
        uint2 st;
        st.x = *(uint32_t*)&p0;
        st.y = *(uint32_t*)&p1;
        *(uint2*)(y16 + (size_t)row * DD + colb) = st;
    }
}

// ======================= global mean pool =======================
__device__ __forceinline__ int lowerb(const int* __restrict__ a, int n, int key) {
    int lo = 0, hi = n;
    while (lo < hi) {
        int mid = (lo + hi) >> 1;
        if (a[mid] < key) lo = mid + 1; else hi = mid;
    }
    return lo;
}
__global__ void __launch_bounds__(512) k_pool(const float* __restrict__ x,
                                              const int* __restrict__ batch,
                                              float* __restrict__ out) {
    __shared__ int sl, sh;
    __shared__ float part[4][128];
    int g = blockIdx.x;
    if (threadIdx.x == 0) {
        sl = lowerb(batch, NN, g);
        sh = lowerb(batch, NN, g + 1);
    }
    __syncthreads();
    int lo = sl, hi = sh;
    int c = threadIdx.x & 127;
    int rchunk = threadIdx.x >> 7;
    float sum = 0.f;
    for (int n = lo + rchunk; n < hi; n += 4) sum += x[(size_t)n * DD + c];
    part[rchunk][c] = sum;
    __syncthreads();
    if (rchunk == 0) {
        float t = part[0][c] + part[1][c] + part[2][c] + part[3][c];
        out[g * DD + c] = t / fmaxf((float)(hi - lo), 1.f);
    }
}

// ======================= launch =======================
extern "C" void kernel_launch(void* const* d_in, const int* in_sizes, int n_in,
                              void* d_out, int out_size) {
    const float* x     = (const float*)d_in[0];
    const int*   ei    = (const int*)d_in[1];
    const int*   batch = (const int*)d_in[2];
    const float* W[3]  = {(const float*)d_in[3],  (const float*)d_in[7],  (const float*)d_in[11]};
    const float* b[3]  = {(const float*)d_in[4],  (const float*)d_in[8],  (const float*)d_in[12]};
    const float* g[3]  = {(const float*)d_in[5],  (const float*)d_in[9],  (const float*)d_in[13]};
    const float* be[3] = {(const float*)d_in[6],  (const float*)d_in[10], (const float*)d_in[14]};
    float* out = (float*)d_out;

    float *y0 = nullptr, *y1 = nullptr;
    __half *a16 = nullptr, *xa16 = nullptr;
    uint32_t* wt = nullptr;
    int* pdeg = nullptr;
    cudaGetSymbolAddress((void**)&y0, g_y0);
    cudaGetSymbolAddress((void**)&y1, g_y1);
    cudaGetSymbolAddress((void**)&a16, g_a16);
    cudaGetSymbolAddress((void**)&xa16, g_xa16);
    cudaGetSymbolAddress((void**)&wt, g_wt);
    cudaGetSymbolAddress((void**)&pdeg, g_deg);

    cudaFuncSetAttribute(k_gemm_fused, cudaFuncAttributeMaxDynamicSharedMemorySize, DYN_SMEM);

    cudaMemsetAsync(pdeg, 0, NN * sizeof(int));
    k_deg_x16<<<DEGB + CVTB, 256>>>(ei, x);
    k_scan_wt<<<4, 1024>>>(W[0], W[1], W[2]);
    k_fill<<<(EE + 255) / 256, 256>>>(ei);

    const int agg_blocks = (NN * 32 + 255) / 256;
    const int gemm_blocks = (NN + TILE_M - 1) / TILE_M;

    // layer 0: gather a16(x) -> xa16; gemm -> y0 (+ a16 fp16 copy)
    k_agg<<<agg_blocks, 256>>>(a16, xa16);
    k_gemm_fused<<<gemm_blocks, 256, DYN_SMEM>>>(xa16, wt + 0 * DD * DD, b[0], g[0], be[0], x, y0, a16);
    // layer 1
    k_agg<<<agg_blocks, 256>>>(a16, xa16);
    k_gemm_fused<<<gemm_blocks, 256, DYN_SMEM>>>(xa16, wt + 1 * DD * DD, b[1], g[1], be[1], y0, y1, a16);
    // layer 2
    k_agg<<<agg_blocks, 256>>>(a16, xa16);
    k_gemm_fused<<<gemm_blocks, 256, DYN_SMEM>>>(xa16, wt + 2 * DD * DD, b[2], g[2], be[2], y1, y0, a16);

    k_pool<<<GG, 512>>>(y0, batch, out);
}

// round 8
// speedup vs baseline: 1.3183x; 1.0288x over previous
#include <cuda_runtime.h>
#include <cuda_fp16.h>
#include <cstdint>
#include <math.h>

#define NN 50000
#define EE 600000
#define DD 128
#define GG 128

// ---------------- device scratch ----------------
__device__ __half g_x16[NN * DD];      // fp16 copy of input x (L0 gather source)
__device__ __half g_h0[NN * DD];       // L0 output (gather+residual source for L1)
__device__ __half g_h1[NN * DD];       // L1 output (gather+residual source for L2)
__device__ __half g_xa16[NN * DD];     // aggregated output scratch
__device__ float  g_y0[NN * DD];       // L2 output fp32 (pool input)
__device__ int    g_deg[NN];
__device__ int    g_rank[EE];
__device__ float  g_dinv[NN];
__device__ int    g_rowptr[NN + 1];
__device__ int2   g_edge[EE];          // packed {src, w_bits}
__device__ uint32_t g_wt[3][DD * DD];  // W^T, tf32 bits, permuted k-layout

__device__ __forceinline__ uint32_t f2tf32(float f) {
    uint32_t r;
    asm("cvt.rna.tf32.f32 %0, %1;" : "=r"(r) : "f"(f));
    return r;
}
__device__ __forceinline__ void mma_tf32(float c[4], const uint32_t a[4], const uint32_t b[2]) {
    asm volatile(
        "mma.sync.aligned.m16n8k8.row.col.f32.tf32.tf32.f32 "
        "{%0,%1,%2,%3}, {%4,%5,%6,%7}, {%8,%9}, {%0,%1,%2,%3};"
        : "+f"(c[0]), "+f"(c[1]), "+f"(c[2]), "+f"(c[3])
        : "r"(a[0]), "r"(a[1]), "r"(a[2]), "r"(a[3]), "r"(b[0]), "r"(b[1]));
}
__device__ __forceinline__ float4 h4tof4(uint2 raw) {
    __half2 h0 = *(__half2*)&raw.x;
    __half2 h1 = *(__half2*)&raw.y;
    float2 f0 = __half22float2(h0);
    float2 f1 = __half22float2(h1);
    return make_float4(f0.x, f0.y, f1.x, f1.y);
}
__device__ __forceinline__ uint2 f4toh4(float a, float b, float c, float d) {
    __half2 p0 = __floats2half2_rn(a, b);
    __half2 p1 = __floats2half2_rn(c, d);
    uint2 st;
    st.x = *(uint32_t*)&p0;
    st.y = *(uint32_t*)&p1;
    return st;
}

// ======================= deg + x->fp16 convert =======================
#define DEGB ((EE + 255) / 256)
#define CVTB ((NN * DD / 8 + 255) / 256)

__global__ void k_deg_x16(const int* __restrict__ ei, const float* __restrict__ x) {
    if (blockIdx.x < DEGB) {
        int e = blockIdx.x * 256 + threadIdx.x;
        if (e < EE) g_rank[e] = atomicAdd(&g_deg[ei[EE + e]], 1);
    } else {
        int i = (blockIdx.x - DEGB) * 256 + threadIdx.x;
        if (i < NN * DD / 8) {
            float4 v0 = *(const float4*)(x + (size_t)i * 8);
            float4 v1 = *(const float4*)(x + (size_t)i * 8 + 4);
            uint2 a = f4toh4(v0.x, v0.y, v0.z, v0.w);
            uint2 b = f4toh4(v1.x, v1.y, v1.z, v1.w);
            *(uint4*)(g_x16 + (size_t)i * 8) = make_uint4(a.x, a.y, b.x, b.y);
        }
    }
}

// ======================= scan + dinv + W^T precompute =======================
__global__ void k_scan_wt(const float* __restrict__ W0, const float* __restrict__ W1,
                          const float* __restrict__ W2) {
    if (blockIdx.x > 0) {
        const float* Ws[3] = {W0, W1, W2};
        int l = blockIdx.x - 1;
        for (int i = threadIdx.x; i < DD * DD; i += 1024) {
            int n = i >> 7;
            int kp = i & 127;
            int k = (kp & ~7) + ((kp & 7) >> 1) + ((kp & 1) << 2);
            g_wt[l][i] = f2tf32(Ws[l][(size_t)k * DD + n]);
        }
        return;
    }
    const int CH = (NN + 1023) / 1024;
    __shared__ int ss[1024];
    int t = threadIdx.x;
    int vals[CH];
    int base = t * CH;
    int loc = 0;
#pragma unroll
    for (int i = 0; i < CH; ++i) {
        int idx = base + i;
        int v = (idx < NN) ? g_deg[idx] : 0;
        if (idx < NN) g_dinv[idx] = rsqrtf((float)(v + 1));
        vals[i] = loc;
        loc += v;
    }
    ss[t] = loc;
    __syncthreads();
    for (int off = 1; off < 1024; off <<= 1) {
        int v = (t >= off) ? ss[t - off] : 0;
        __syncthreads();
        ss[t] += v;
        __syncthreads();
    }
    int pre = (t > 0) ? ss[t - 1] : 0;
#pragma unroll
    for (int i = 0; i < CH; ++i) {
        int idx = base + i;
        if (idx < NN) g_rowptr[idx] = pre + vals[i];
    }
    if (t == 1023) g_rowptr[NN] = ss[1023];
}

// atomic-free CSR fill, packed edge meta
__global__ void k_fill(const int* __restrict__ ei) {
    int e = blockIdx.x * blockDim.x + threadIdx.x;
    if (e < EE) {
        int s = ei[e];
        int d = ei[EE + e];
        int pos = g_rowptr[d] + g_rank[e];
        g_edge[pos] = make_int2(s, __float_as_int(g_dinv[s] * g_dinv[d]));
    }
}

// ======================= aggregation (fp16 gather, packed meta) =======================
__global__ void __launch_bounds__(256) k_agg(const __half* __restrict__ a16,
                                             __half* __restrict__ xa16) {
    int w = (blockIdx.x * blockDim.x + threadIdx.x) >> 5;
    int lane = threadIdx.x & 31;
    if (w >= NN) return;
    int col = lane * 4;

    float di = g_dinv[w];
    float sw = di * di;
    float4 a0 = h4tof4(*(const uint2*)(a16 + (size_t)w * DD + col));
    a0.x *= sw; a0.y *= sw; a0.z *= sw; a0.w *= sw;
    float4 a1 = make_float4(0.f, 0.f, 0.f, 0.f);
    float4 a2 = make_float4(0.f, 0.f, 0.f, 0.f);
    float4 a3 = make_float4(0.f, 0.f, 0.f, 0.f);

    int e0 = g_rowptr[w], e1 = g_rowptr[w + 1];
    int e = e0;
    for (; e + 4 <= e1; e += 4) {
        int2 m0 = __ldg(&g_edge[e + 0]);
        int2 m1 = __ldg(&g_edge[e + 1]);
        int2 m2 = __ldg(&g_edge[e + 2]);
        int2 m3 = __ldg(&g_edge[e + 3]);
        float4 h0 = h4tof4(*(const uint2*)(a16 + (size_t)m0.x * DD + col));
        float4 h1 = h4tof4(*(const uint2*)(a16 + (size_t)m1.x * DD + col));
        float4 h2 = h4tof4(*(const uint2*)(a16 + (size_t)m2.x * DD + col));
        float4 h3 = h4tof4(*(const uint2*)(a16 + (size_t)m3.x * DD + col));
        float w0 = __int_as_float(m0.y), w1 = __int_as_float(m1.y);
        float w2 = __int_as_float(m2.y), w3 = __int_as_float(m3.y);
        a0.x += w0 * h0.x; a0.y += w0 * h0.y; a0.z += w0 * h0.z; a0.w += w0 * h0.w;
        a1.x += w1 * h1.x; a1.y += w1 * h1.y; a1.z += w1 * h1.z; a1.w += w1 * h1.w;
        a2.x += w2 * h2.x; a2.y += w2 * h2.y; a2.z += w2 * h2.z; a2.w += w2 * h2.w;
        a3.x += w3 * h3.x; a3.y += w3 * h3.y; a3.z += w3 * h3.z; a3.w += w3 * h3.w;
    }
    for (; e < e1; ++e) {
        int2 m = __ldg(&g_edge[e]);
        float wt = __int_as_float(m.y);
        float4 hs = h4tof4(*(const uint2*)(a16 + (size_t)m.x * DD + col));
        a0.x += wt * hs.x; a0.y += wt * hs.y; a0.z += wt * hs.z; a0.w += wt * hs.w;
    }
    a0.x += a1.x + a2.x + a3.x;
    a0.y += a1.y + a2.y + a3.y;
    a0.z += a1.z + a2.z + a3.z;
    a0.w += a1.w + a2.w + a3.w;
    *(uint2*)(xa16 + (size_t)w * DD + col) = f4toh4(a0.x, a0.y, a0.z, a0.w);
}

// ======================= persistent tf32 GEMM + fused epilogue =======================
#define TILE_M 64
#define SST 132
#define TILES ((NN + TILE_M - 1) / TILE_M)
#define GEMM_GRID 296
#define DYN_SMEM ((TILE_M + 128) * SST * 4)

template <bool RES16, bool OUT16>
__global__ void __launch_bounds__(256) k_gemm(
    const __half* __restrict__ A16, const uint32_t* __restrict__ Wt,
    const float* __restrict__ bias, const float* __restrict__ gamma,
    const float* __restrict__ beta,
    const float* __restrict__ xres32, const __half* __restrict__ xres16,
    float* __restrict__ y32, __half* __restrict__ y16) {
    extern __shared__ float smem[];
    float* As = smem;
    float* Bs = smem + TILE_M * SST;
    uint32_t* Asu = (uint32_t*)As;
    uint32_t* Bsu = (uint32_t*)Bs;
    __shared__ float s_b[128], s_g[128], s_be[128];

    int tid = threadIdx.x;
    int wid = tid >> 5;
    int lane = tid & 31;

    if (tid < 128) { s_b[tid] = bias[tid]; s_g[tid] = gamma[tid]; s_be[tid] = beta[tid]; }
    // stage B once
    for (int i = tid; i < 128 * 32; i += 256) {
        int n = i >> 5;
        int c4 = (i & 31) << 2;
        *(uint4*)&Bsu[n * SST + c4] = *(const uint4*)&Wt[n * DD + c4];
    }

    const int wm = (wid >> 2) * 32;
    const int wn = (wid & 3) * 32;
    const int qrow = lane >> 2;
    const int qcol = lane & 3;
    const int colb = lane * 4;

    for (int t = blockIdx.x; t < TILES; t += GEMM_GRID) {
        int m0 = t * TILE_M;
        __syncthreads();   // prior epilogue reads of As done (and B ready on iter 0)

        // stage A from fp16 (exact fp16->tf32), permuted-k
        for (int i = tid; i < TILE_M * 16; i += 256) {
            int m = i >> 4;
            int c = (i & 15) << 3;
            int gm = m0 + m;
            uint4 raw = (gm < NN) ? *(const uint4*)(A16 + (size_t)gm * DD + c)
                                  : make_uint4(0, 0, 0, 0);
            float4 f0 = h4tof4(make_uint2(raw.x, raw.y));
            float4 f1 = h4tof4(make_uint2(raw.z, raw.w));
            float f[8] = {f0.x, f0.y, f0.z, f0.w, f1.x, f1.y, f1.z, f1.w};
            int base = m * SST + c;
#pragma unroll
            for (int j = 0; j < 8; ++j)
                Asu[base + (((j & 3) << 1) | (j >> 2))] = f2tf32(f[j]);
        }
        __syncthreads();

        float c[2][4][4];
#pragma unroll
        for (int mt = 0; mt < 2; ++mt)
#pragma unroll
            for (int nt = 0; nt < 4; ++nt)
#pragma unroll
                for (int j = 0; j < 4; ++j) c[mt][nt][j] = 0.f;

#pragma unroll
        for (int ks = 0; ks < 16; ++ks) {
            int k0 = ks * 8;
            uint32_t a[2][4], b[4][2];
#pragma unroll
            for (int mt = 0; mt < 2; ++mt) {
                int r = wm + mt * 16 + qrow;
                uint2 lo = *(const uint2*)&Asu[r * SST + k0 + 2 * qcol];
                uint2 hi = *(const uint2*)&Asu[(r + 8) * SST + k0 + 2 * qcol];
                a[mt][0] = lo.x; a[mt][1] = hi.x; a[mt][2] = lo.y; a[mt][3] = hi.y;
            }
#pragma unroll
            for (int nt = 0; nt < 4; ++nt) {
                int n = wn + nt * 8 + qrow;
                uint2 bb = *(const uint2*)&Bsu[n * SST + k0 + 2 * qcol];
                b[nt][0] = bb.x; b[nt][1] = bb.y;
            }
#pragma unroll
            for (int mt = 0; mt < 2; ++mt)
#pragma unroll
                for (int nt = 0; nt < 4; ++nt)
                    mma_tf32(c[mt][nt], a[mt], b[nt]);
        }

        __syncthreads();
#pragma unroll
        for (int mt = 0; mt < 2; ++mt) {
            int r = wm + mt * 16 + qrow;
#pragma unroll
            for (int nt = 0; nt < 4; ++nt) {
                int cc = wn + nt * 8 + qcol * 2;
                *(float2*)&As[r * SST + cc] = make_float2(c[mt][nt][0], c[mt][nt][1]);
                *(float2*)&As[(r + 8) * SST + cc] = make_float2(c[mt][nt][2], c[mt][nt][3]);
            }
        }
        __syncthreads();

        float4 bv = *(const float4*)(s_b + colb);
        float4 gv = *(const float4*)(s_g + colb);
        float4 bev = *(const float4*)(s_be + colb);
#pragma unroll
        for (int rr = 0; rr < 8; ++rr) {
            int r = wid * 8 + rr;
            int row = m0 + r;
            if (row >= NN) break;
            float4 d = *(const float4*)&As[r * SST + colb];
            d.x += bv.x; d.y += bv.y; d.z += bv.z; d.w += bv.w;
            float s1 = d.x + d.y + d.z + d.w;
#pragma unroll
            for (int o = 16; o; o >>= 1) s1 += __shfl_xor_sync(0xffffffffu, s1, o);
            float mu = s1 * (1.f / 128.f);
            float d0 = d.x - mu, d1 = d.y - mu, d2 = d.z - mu, d3 = d.w - mu;
            float s2 = d0 * d0 + d1 * d1 + d2 * d2 + d3 * d3;
#pragma unroll
            for (int o = 16; o; o >>= 1) s2 += __shfl_xor_sync(0xffffffffu, s2, o);
            float rs = rsqrtf(s2 * (1.f / 128.f) + 1e-5f);

            float4 xv;
            if (RES16) xv = h4tof4(*(const uint2*)(xres16 + (size_t)row * DD + colb));
            else       xv = *(const float4*)(xres32 + (size_t)row * DD + colb);
            float v0 = d0 * rs * gv.x + bev.x + xv.x;
            float v1 = d1 * rs * gv.y + bev.y + xv.y;
            float v2 = d2 * rs * gv.z + bev.z + xv.z;
            float v3 = d3 * rs * gv.w + bev.w + xv.w;
            v0 = v0 / (1.f + __expf(-v0));
            v1 = v1 / (1.f + __expf(-v1));
            v2 = v2 / (1.f + __expf(-v2));
            v3 = v3 / (1.f + __expf(-v3));
            if (OUT16) *(uint2*)(y16 + (size_t)row * DD + colb) = f4toh4(v0, v1, v2, v3);
            else       *(float4*)(y32 + (size_t)row * DD + colb) = make_float4(v0, v1, v2, v3);
        }
    }
}

// ======================= global mean pool =======================
__device__ __forceinline__ int lowerb(const int* __restrict__ a, int n, int key) {
    int lo = 0, hi = n;
    while (lo < hi) {
        int mid = (lo + hi) >> 1;
        if (a[mid] < key) lo = mid + 1; else hi = mid;
    }
    return lo;
}
__global__ void __launch_bounds__(1024) k_pool(const float* __restrict__ x,
                                               const int* __restrict__ batch,
                                               float* __restrict__ out) {
    __shared__ int sl, sh;
    __shared__ float part[8][128];
    int g = blockIdx.x;
    if (threadIdx.x == 0) {
        sl = lowerb(batch, NN, g);
        sh = lowerb(batch, NN, g + 1);
    }
    __syncthreads();
    int lo = sl, hi = sh;
    int c = threadIdx.x & 127;
    int rchunk = threadIdx.x >> 7;   // 0..7
    float s0 = 0.f, s1 = 0.f;
    int n = lo + rchunk;
    for (; n + 8 < hi; n += 16) {
        s0 += x[(size_t)n * DD + c];
        s1 += x[(size_t)(n + 8) * DD + c];
    }
    if (n < hi) s0 += x[(size_t)n * DD + c];
    part[rchunk][c] = s0 + s1;
    __syncthreads();
    if (rchunk == 0) {
        float t = 0.f;
#pragma unroll
        for (int j = 0; j < 8; ++j) t += part[j][c];
        out[g * DD + c] = t / fmaxf((float)(hi - lo), 1.f);
    }
}

// ======================= launch =======================
extern "C" void kernel_launch(void* const* d_in, const int* in_sizes, int n_in,
                              void* d_out, int out_size) {
    const float* x     = (const float*)d_in[0];
    const int*   ei    = (const int*)d_in[1];
    const int*   batch = (const int*)d_in[2];
    const float* W[3]  = {(const float*)d_in[3],  (const float*)d_in[7],  (const float*)d_in[11]};
    const float* b[3]  = {(const float*)d_in[4],  (const float*)d_in[8],  (const float*)d_in[12]};
    const float* g[3]  = {(const float*)d_in[5],  (const float*)d_in[9],  (const float*)d_in[13]};
    const float* be[3] = {(const float*)d_in[6],  (const float*)d_in[10], (const float*)d_in[14]};
    float* out = (float*)d_out;

    float* y0 = nullptr;
    __half *x16 = nullptr, *h0 = nullptr, *h1 = nullptr, *xa16 = nullptr;
    uint32_t* wt = nullptr;
    int* pdeg = nullptr;
    cudaGetSymbolAddress((void**)&y0, g_y0);
    cudaGetSymbolAddress((void**)&x16, g_x16);
    cudaGetSymbolAddress((void**)&h0, g_h0);
    cudaGetSymbolAddress((void**)&h1, g_h1);
    cudaGetSymbolAddress((void**)&xa16, g_xa16);
    cudaGetSymbolAddress((void**)&wt, g_wt);
    cudaGetSymbolAddress((void**)&pdeg, g_deg);

    cudaFuncSetAttribute(k_gemm<false, true>, cudaFuncAttributeMaxDynamicSharedMemorySize, DYN_SMEM);
    cudaFuncSetAttribute(k_gemm<true, true>, cudaFuncAttributeMaxDynamicSharedMemorySize, DYN_SMEM);
    cudaFuncSetAttribute(k_gemm<true, false>, cudaFuncAttributeMaxDynamicSharedMemorySize, DYN_SMEM);

    cudaMemsetAsync(pdeg, 0, NN * sizeof(int));
    k_deg_x16<<<DEGB + CVTB, 256>>>(ei, x);
    k_scan_wt<<<4, 1024>>>(W[0], W[1], W[2]);
    k_fill<<<(EE + 255) / 256, 256>>>(ei);

    const int agg_blocks = (NN * 32 + 255) / 256;

    // L0: gather x16 -> xa16; gemm(res=x fp32) -> h0 (fp16)
    k_agg<<<agg_blocks, 256>>>(x16, xa16);
    k_gemm<false, true><<<GEMM_GRID, 256, DYN_SMEM>>>(xa16, wt + 0 * DD * DD, b[0], g[0], be[0], x, nullptr, nullptr, h0);
    // L1: gather h0 -> xa16; gemm(res=h0 fp16) -> h1 (fp16)
    k_agg<<<agg_blocks, 256>>>(h0, xa16);
    k_gemm<true, true><<<GEMM_GRID, 256, DYN_SMEM>>>(xa16, wt + 1 * DD * DD, b[1], g[1], be[1], nullptr, h0, nullptr, h1);
    // L2: gather h1 -> xa16; gemm(res=h1 fp16) -> y0 (fp32)
    k_agg<<<agg_blocks, 256>>>(h1, xa16);
    k_gemm<true, false><<<GEMM_GRID, 256, DYN_SMEM>>>(xa16, wt + 2 * DD * DD, b[2], g[2], be[2], nullptr, h1, y0, nullptr);

    k_pool<<<GG, 1024>>>(y0, batch, out);
}